// round 11
// baseline (speedup 1.0000x reference)
#include <cuda_runtime.h>

#define NN 1395
#define EE 44640
#define GB 592

// prefetch geometry: 778 prefetch blocks x 12288 float4 (192KB) = ~153MB of fc3_w
#define PFCHUNK 12288

// ---------------- scratch (device globals) ----------------------------------
__device__ __align__(16) float g_xw[NN * 3];
__device__ __align__(16) float g_acc[NN * 3 + 1];
__device__ int   g_deg[NN];
__device__ float g_dinv[NN];
__device__ unsigned g_pk[EE];
__device__ __align__(16) float g_v1[2048];
__device__ __align__(16) float g_v2[4096];
__device__ __align__(16) float g_c1[32 * 58 * 58];
__device__ __align__(16) float g_c2[32 * 54 * 54];
__device__ __align__(16) float g_c3[64 * 52 * 52];
__device__ __align__(16) float g_c4[64 * 50 * 50];
__device__ __align__(16) float g_f3[2048];
__device__ __align__(16) float g_f4[2048];
__device__ float g_sink[64];     // prefetch sink; never read

// ---------------- software grid barrier (used only inside kB) ----------------
__device__ unsigned g_cnt = 0;
__device__ volatile unsigned g_rel = 0;

__device__ __forceinline__ void gsync(unsigned nb) {
    __syncthreads();
    if (threadIdx.x == 0) {
        __threadfence();
        unsigned gen = g_rel;
        if (atomicAdd(&g_cnt, 1u) == nb - 1u) {
            g_cnt = 0u;
            __threadfence();
            g_rel = gen + 1u;
        } else {
            while (g_rel == gen) __nanosleep(64);
        }
    }
    __syncthreads();
}

__device__ __forceinline__ float warp_red(float a) {
#pragma unroll
    for (int o = 16; o > 0; o >>= 1)
        a += __shfl_down_sync(0xFFFFFFFFu, a, o);
    return a;
}

// ---------------- fc3_w L2 prefetch (runs on spare conv-kernel blocks) -------
__device__ __forceinline__ void pf_impl(const float* __restrict__ fc3_w, int pid) {
    const float4* p = (const float4*)fc3_w + (size_t)pid * PFCHUNK;
    float s = 0.f;
#pragma unroll 4
    for (int i = threadIdx.x; i < PFCHUNK; i += 256) {
        float4 v = __ldcg(&p[i]);
        s += v.x + v.y + v.z + v.w;
    }
    if (threadIdx.x == 0) g_sink[pid & 63] = s;
}

// ---------------- edge pass: dtype detect + pack + degree + f3 seed ----------
__global__ void k_edge(const void* __restrict__ ei, const float* __restrict__ fc3_b) {
    int e = blockIdx.x * 256 + threadIdx.x;
    if (e < 2048) g_f3[e] = fc3_b[e];
    const unsigned* u = (const unsigned*)ei;
    unsigned odd = (e < EE) ? u[2 * e + 1] : 0u;
    int any = __syncthreads_or(odd != 0u);    // int64 <=> odd dwords all zero
    int idx64 = !any;
    if (e >= EE) return;
    int s, d;
    if (idx64) {
        s = (int)((const long long*)ei)[e];
        d = (int)((const long long*)ei)[EE + e];
    } else {
        s = ((const int*)ei)[e];
        d = ((const int*)ei)[EE + e];
    }
    unsigned pk = 0xFFFFFFFFu;
    if (s >= 0 && s < NN && d >= 0 && d < NN) {
        pk = (unsigned)s | ((unsigned)d << 11);
        atomicAdd(&g_deg[d], 1);
    }
    g_pk[e] = pk;
}

// ---------------- node stage 1 ------------------------------------------------
__global__ void k_node1(const float* __restrict__ x, const float* __restrict__ W1) {
    int i = blockIdx.x * blockDim.x + threadIdx.x;
    if (i >= NN) return;
    float di = rsqrtf((float)(g_deg[i] + 1));
    g_deg[i] = 0;                 // self-clear for next graph replay
    g_dinv[i] = di;
    float x3 = x[i * 6 + 3], x4 = x[i * 6 + 4], x5 = x[i * 6 + 5];
    float d2 = di * di;
#pragma unroll
    for (int c = 0; c < 3; c++) {
        float xw = x3 * W1[9 + c] + x4 * W1[12 + c] + x5 * W1[15 + c];
        g_xw[i * 3 + c] = xw;
        g_acc[i * 3 + c] = d2 * xw;
    }
}

// ---------------- scatter (global atomics) -----------------------------------
__global__ void k_scat() {
    int e = blockIdx.x * blockDim.x + threadIdx.x;
    if (e >= EE) return;
    unsigned pk = g_pk[e];
    if (pk == 0xFFFFFFFFu) return;
    int s = pk & 2047, d = pk >> 11;
    float n = g_dinv[s] * g_dinv[d];
    atomicAdd(&g_acc[d * 3 + 0], n * g_xw[s * 3 + 0]);
    atomicAdd(&g_acc[d * 3 + 1], n * g_xw[s * 3 + 1]);
    atomicAdd(&g_acc[d * 3 + 2], n * g_xw[s * 3 + 2]);
}

// ---------------- node stage 2 ------------------------------------------------
__global__ void k_node2(const float* __restrict__ b1, const float* __restrict__ W2) {
    int i = blockIdx.x * blockDim.x + threadIdx.x;
    if (i >= NN) return;
    float h[3];
#pragma unroll
    for (int c = 0; c < 3; c++) {
        float v = g_acc[i * 3 + c] + b1[c];
        h[c] = (v >= 0.f) ? v : 0.2f * v;
    }
    float di = g_dinv[i];
    float d2 = di * di;
#pragma unroll
    for (int c = 0; c < 3; c++) {
        float xw = h[0] * W2[c] + h[1] * W2[3 + c] + h[2] * W2[6 + c];
        g_xw[i * 3 + c] = xw;
        g_acc[i * 3 + c] = d2 * xw;
    }
}

// ---------------- fc1 [2048 x 4185] with fused leaky(acc + b2) ---------------
__global__ void k_fc1(const float* __restrict__ W, const float* __restrict__ b,
                      const float* __restrict__ b2) {
    __shared__ __align__(16) float xs[4185];
    float bb0 = b2[0], bb1 = b2[1], bb2 = b2[2];
    for (int i = threadIdx.x; i < 4185; i += 256) {
        int c = i % 3;
        float bias = (c == 0) ? bb0 : (c == 1 ? bb1 : bb2);
        float v = g_acc[i] + bias;
        xs[i] = (v >= 0.f) ? v : 0.2f * v;
    }
    __syncthreads();
    int gt = blockIdx.x * 256 + threadIdx.x;
    int warp = gt >> 5, lane = gt & 31;
    if (warp >= 2048) return;
    const float* wr = W + (size_t)warp * 4185;
    float a = 0.f;
#pragma unroll 4
    for (int i = lane; i < 4185; i += 32) a += __ldcs(&wr[i]) * xs[i];
    a = warp_red(a);
    if (lane == 0) g_v1[warp] = a + b[warp];
}

// ---------------- fc2 [4096 x 2048] + seed conv accumulators -----------------
__global__ void k_fc2(const float* __restrict__ W, const float* __restrict__ b,
                      const float* __restrict__ c2_b, const float* __restrict__ c3_b,
                      const float* __restrict__ c4_b) {
    __shared__ __align__(16) float xs[2048];
    {
        int gt = blockIdx.x * 256 + threadIdx.x;
        int T = gridDim.x * 256;
        for (int i = gt; i < 32 * 54 * 54; i += T) g_c2[i] = c2_b[i / (54 * 54)];
        for (int i = gt; i < 64 * 52 * 52; i += T) g_c3[i] = c3_b[i / (52 * 52)];
        for (int i = gt; i < 64 * 50 * 50; i += T) g_c4[i] = c4_b[i / (50 * 50)];
    }
    for (int i = threadIdx.x; i < 2048; i += 256) xs[i] = g_v1[i];
    __syncthreads();
    int gt = blockIdx.x * 256 + threadIdx.x;
    int warp = gt >> 5, lane = gt & 31;
    if (warp >= 4096) return;
    const float4* w4 = (const float4*)(W + (size_t)warp * 2048);
    const float4* xs4 = (const float4*)xs;
    float a = 0.f;
#pragma unroll 4
    for (int i = lane; i < 512; i += 32) {
        float4 w = __ldcs(&w4[i]);
        float4 xv = xs4[i];
        a += w.x * xv.x + w.y * xv.y + w.z * xv.z + w.w * xv.w;
    }
    a = warp_red(a);
    if (lane == 0) g_v2[warp] = a + b[warp];
}

// ---------------- conv (CI-split, REDG accumulation) -------------------------
template <int CI, int KH, int KW, int OCB, int SPLIT>
__device__ __forceinline__ void conv_impl(const float* __restrict__ in,
                                          const float* __restrict__ w,
                                          const float* __restrict__ bia,
                                          float* __restrict__ out,
                                          int H, int W, int OH, int OW) {
    const int CIP = CI / SPLIT;
    __shared__ float sw[OCB * CIP * KH * KW];
    int ocg = blockIdx.x / SPLIT;
    int part = blockIdx.x - ocg * SPLIT;
    int oc0 = ocg * OCB;
    int ic0 = part * CIP;
    for (int i = threadIdx.x; i < OCB * CIP * KH * KW; i += blockDim.x) {
        int o = i / (CIP * KH * KW);
        int rem = i - o * (CIP * KH * KW);
        int ic = rem / (KH * KW);
        int k = rem - ic * (KH * KW);
        sw[i] = w[((size_t)(oc0 + o) * CI + ic0 + ic) * (KH * KW) + k];
    }
    __syncthreads();

    int p = blockIdx.y * blockDim.x + threadIdx.x;
    if (p >= OH * OW) return;
    int oy = p / OW, ox = p - oy * OW;
    float acc[OCB];
#pragma unroll
    for (int o = 0; o < OCB; o++) acc[o] = (SPLIT == 1) ? bia[oc0 + o] : 0.f;

    for (int ic = 0; ic < CIP; ic++) {
        const float* ip = in + ((size_t)(ic0 + ic) * H + oy) * W + ox;
        const float* wp = sw + ic * KH * KW;
#pragma unroll
        for (int i = 0; i < KH; i++)
#pragma unroll
            for (int j = 0; j < KW; j++) {
                float v = ip[i * W + j];
#pragma unroll
                for (int o = 0; o < OCB; o++)
                    acc[o] += wp[o * CIP * KH * KW + i * KW + j] * v;
            }
    }
#pragma unroll
    for (int o = 0; o < OCB; o++) {
        size_t oi = ((size_t)(oc0 + o) * OH + oy) * OW + ox;
        if (SPLIT == 1) out[oi] = acc[o];
        else atomicAdd(&out[oi], acc[o]);
    }
}

// conv kernels with fc3_w prefetch riding on extra blockIdx.x groups
__global__ void k_conv1(const float* __restrict__ w, const float* __restrict__ b,
                        const float* __restrict__ f3w) {
    if (blockIdx.x < 8)
        conv_impl<1, 7, 7, 4, 1>(g_v2, w, b, g_c1, 64, 64, 58, 58);
    else
        pf_impl(f3w, 0 + (blockIdx.x - 8) * gridDim.y + blockIdx.y);
}
__global__ void k_conv2(const float* __restrict__ w, const float* __restrict__ b,
                        const float* __restrict__ f3w) {
    if (blockIdx.x < 32)
        conv_impl<32, 5, 5, 4, 4>(g_c1, w, b, g_c2, 58, 58, 54, 54);
    else
        pf_impl(f3w, 112 + (blockIdx.x - 32) * gridDim.y + blockIdx.y);
}
__global__ void k_conv3(const float* __restrict__ w, const float* __restrict__ b,
                        const float* __restrict__ f3w) {
    if (blockIdx.x < 16)
        conv_impl<32, 3, 3, 8, 2>(g_c2, w, b, g_c3, 54, 54, 52, 52);
    else
        pf_impl(f3w, 328 + (blockIdx.x - 16) * gridDim.y + blockIdx.y);
}
__global__ void k_conv4(const float* __restrict__ w, const float* __restrict__ b,
                        const float* __restrict__ f3w) {
    if (blockIdx.x < 32)
        conv_impl<64, 3, 3, 8, 4>(g_c3, w, b, g_c4, 52, 52, 50, 50);
    else
        pf_impl(f3w, 548 + (blockIdx.x - 32) * gridDim.y + blockIdx.y);
}

// ---------------- kB: fc3 (8-row groups, deeper MLP) + fc4 + fc5 -------------
extern "C" __global__ void __launch_bounds__(256, 4) kB(
    const float* __restrict__ fc3_w,
    const float* __restrict__ fc4_w, const float* __restrict__ fc4_b,
    const float* __restrict__ fc5_w, const float* __restrict__ fc5_b,
    float* __restrict__ out) {
    __shared__ __align__(16) float xs[2048];
    __shared__ float sred[8];

    // fc3: 2048x160000. 4096 chunks = 256 row-groups(8 rows) x 16 col-splits.
    const int NC4 = 40000, CHUNK = 2500, NCHUNK = 4096;
    for (int c = blockIdx.x; c < NCHUNK; c += GB) {
        int rg = c >> 4, cs = c & 15;
        int r0 = rg * 8;
        if (threadIdx.x < 8) sred[threadIdx.x] = 0.f;
        __syncthreads();
        const float4* x4 = (const float4*)g_c4 + cs * CHUNK;
        const float4* w4 = (const float4*)fc3_w + (size_t)r0 * NC4 + cs * CHUNK;
        float a[8];
#pragma unroll
        for (int k = 0; k < 8; k++) a[k] = 0.f;
#pragma unroll 2
        for (int i = threadIdx.x; i < CHUNK; i += 256) {
            float4 xv = x4[i];
#pragma unroll
            for (int k = 0; k < 8; k++) {
                float4 w = __ldcs(&w4[i + k * NC4]);
                a[k] += w.x * xv.x + w.y * xv.y + w.z * xv.z + w.w * xv.w;
            }
        }
#pragma unroll
        for (int k = 0; k < 8; k++) a[k] = warp_red(a[k]);
        if ((threadIdx.x & 31) == 0) {
#pragma unroll
            for (int k = 0; k < 8; k++) atomicAdd(&sred[k], a[k]);
        }
        __syncthreads();
        if (threadIdx.x < 8) atomicAdd(&g_f3[r0 + threadIdx.x], sred[threadIdx.x]);
        __syncthreads();
    }
    gsync(GB);

    // fc4: 2048x2048, warp per row
    {
        for (int i = threadIdx.x; i < 2048; i += 256) xs[i] = __ldcg(&g_f3[i]);
        __syncthreads();
        int gt = blockIdx.x * 256 + threadIdx.x;
        int warp = gt >> 5, lane = gt & 31, nwarp = (GB * 256) >> 5;
        const float4* xs4 = (const float4*)xs;
        for (int r = warp; r < 2048; r += nwarp) {
            const float4* w4 = (const float4*)(fc4_w + (size_t)r * 2048);
            float a = 0.f;
#pragma unroll 4
            for (int i = lane; i < 512; i += 32) {
                float4 w = __ldcs(&w4[i]);
                float4 xv = xs4[i];
                a += w.x * xv.x + w.y * xv.y + w.z * xv.z + w.w * xv.w;
            }
            a = warp_red(a);
            if (lane == 0) g_f4[r] = a + fc4_b[r];
        }
    }
    gsync(GB);

    // fc5: 48x2048 -> out
    {
        for (int i = threadIdx.x; i < 2048; i += 256) xs[i] = __ldcg(&g_f4[i]);
        __syncthreads();
        int gt = blockIdx.x * 256 + threadIdx.x;
        int warp = gt >> 5, lane = gt & 31;
        if (warp < 48) {
            const float4* w4 = (const float4*)(fc5_w + (size_t)warp * 2048);
            const float4* xs4 = (const float4*)xs;
            float a = 0.f;
            for (int i = lane; i < 512; i += 32) {
                float4 w = w4[i];
                float4 xv = xs4[i];
                a += w.x * xv.x + w.y * xv.y + w.z * xv.z + w.w * xv.w;
            }
            a = warp_red(a);
            if (lane == 0) out[warp] = a + fc5_b[warp];
        }
    }
}

// ---------------- launcher ---------------------------------------------------
extern "C" void kernel_launch(void* const* d_in, const int* in_sizes, int n_in,
                              void* d_out, int out_size) {
    const float* x     = (const float*)d_in[0];
    const void*  ei    = d_in[1];
    const float* W1    = (const float*)d_in[2];
    const float* b1    = (const float*)d_in[3];
    const float* W2    = (const float*)d_in[4];
    const float* b2    = (const float*)d_in[5];
    const float* fc1_w = (const float*)d_in[6];
    const float* fc1_b = (const float*)d_in[7];
    const float* fc2_w = (const float*)d_in[8];
    const float* fc2_b = (const float*)d_in[9];
    const float* c1_w  = (const float*)d_in[10];
    const float* c1_b  = (const float*)d_in[11];
    const float* c2_w  = (const float*)d_in[12];
    const float* c2_b  = (const float*)d_in[13];
    const float* c3_w  = (const float*)d_in[14];
    const float* c3_b  = (const float*)d_in[15];
    const float* c4_w  = (const float*)d_in[16];
    const float* c4_b  = (const float*)d_in[17];
    const float* fc3_w = (const float*)d_in[18];
    const float* fc3_b = (const float*)d_in[19];
    const float* fc4_w = (const float*)d_in[20];
    const float* fc4_b = (const float*)d_in[21];
    const float* fc5_w = (const float*)d_in[22];
    const float* fc5_b = (const float*)d_in[23];
    float* out = (float*)d_out;

    const int NB_N = (NN + 255) / 256;
    const int NB_E = (EE + 255) / 256;

    k_edge<<<NB_E, 256>>>(ei, fc3_b);
    k_node1<<<NB_N, 256>>>(x, W1);
    k_scat<<<NB_E, 256>>>();
    k_node2<<<NB_N, 256>>>(b1, W2);
    k_scat<<<NB_E, 256>>>();

    k_fc1<<<256, 256>>>(fc1_w, fc1_b, b2);
    k_fc2<<<512, 256>>>(fc2_w, fc2_b, c2_b, c3_b, c4_b);

    // conv chain with fc3_w L2 prefetch on extra blockIdx.x groups
    {
        dim3 g1(8 + 8, (58 * 58 + 255) / 256);    // 112 pf blocks
        k_conv1<<<g1, 256>>>(c1_w, c1_b, fc3_w);
        dim3 g2(32 + 18, (54 * 54 + 255) / 256);  // 216 pf blocks
        k_conv2<<<g2, 256>>>(c2_w, c2_b, fc3_w);
        dim3 g3(16 + 20, (52 * 52 + 255) / 256);  // 220 pf blocks
        k_conv3<<<g3, 256>>>(c3_w, c3_b, fc3_w);
        dim3 g4(32 + 23, (50 * 50 + 255) / 256);  // 230 pf blocks
        k_conv4<<<g4, 256>>>(c4_w, c4_b, fc3_w);
    }

    kB<<<GB, 256>>>(fc3_w, fc4_w, fc4_b, fc5_w, fc5_b, out);
}

// round 12
// speedup vs baseline: 1.0513x; 1.0513x over previous
#include <cuda_runtime.h>

#define NN 1395
#define EE 44640
#define G1 175          // ceil(EE/256): GCN fused kernel grid
#define GB 592

// ---------------- scratch (device globals) ----------------------------------
__device__ __align__(16) float g_xw[NN * 3];
__device__ __align__(16) float g_acc[NN * 3 + 1];
__device__ int   g_deg[NN];
__device__ float g_dinv[NN];
__device__ unsigned g_pk[EE];
__device__ __align__(16) float g_v1[2048];
__device__ __align__(16) float g_v2[4096];
__device__ __align__(16) float g_c1[32 * 58 * 58];
__device__ __align__(16) float g_c2[32 * 54 * 54];
__device__ __align__(16) float g_c3[64 * 52 * 52];
__device__ __align__(16) float g_c4[64 * 50 * 50];
__device__ __align__(16) float g_f3[2048];
__device__ __align__(16) float g_f4[2048];

// ---------------- software grid barrier (generation-based) ------------------
__device__ unsigned g_cnt = 0;
__device__ volatile unsigned g_rel = 0;

__device__ __forceinline__ void gsync(unsigned nb) {
    __syncthreads();
    if (threadIdx.x == 0) {
        __threadfence();
        unsigned gen = g_rel;
        if (atomicAdd(&g_cnt, 1u) == nb - 1u) {
            g_cnt = 0u;
            __threadfence();
            g_rel = gen + 1u;
        } else {
            while (g_rel == gen) __nanosleep(64);
        }
    }
    __syncthreads();
}

__device__ __forceinline__ float warp_red(float a) {
#pragma unroll
    for (int o = 16; o > 0; o >>= 1)
        a += __shfl_down_sync(0xFFFFFFFFu, a, o);
    return a;
}

// ---------------- kernel 1: whole GCN (edge-grain persistent, 175 blocks) ----
extern "C" __global__ void __launch_bounds__(256, 4) k_gcn(
    const float* __restrict__ x, const void* __restrict__ ei,
    const float* __restrict__ W1, const float* __restrict__ b1,
    const float* __restrict__ W2, const float* __restrict__ fc3_b) {
    const int T = G1 * 256;
    const int gt = blockIdx.x * 256 + threadIdx.x;

    // s0: seed g_f3 (fc3 bias); dtype detect; pack edges + degree count
    for (int i = gt; i < 2048; i += T) g_f3[i] = fc3_b[i];
    {
        int e = gt;
        const unsigned* u = (const unsigned*)ei;
        unsigned odd = (e < EE) ? u[2 * e + 1] : 0u;
        int any = __syncthreads_or(odd != 0u);   // per-block slice: int64 <=> all zero
        int idx64 = !any;
        if (e < EE) {
            int s, d;
            if (idx64) {
                s = (int)((const long long*)ei)[e];
                d = (int)((const long long*)ei)[EE + e];
            } else {
                s = ((const int*)ei)[e];
                d = ((const int*)ei)[EE + e];
            }
            unsigned pk = 0xFFFFFFFFu;
            if (s >= 0 && s < NN && d >= 0 && d < NN) {
                pk = (unsigned)s | ((unsigned)d << 11);
                atomicAdd(&g_deg[d], 1);
            }
            g_pk[e] = pk;
        }
    }
    gsync(G1);

    // s1: node1 = dinv + xw1 + self term (x[:, :3] zeroed => cols 3..5 only)
    if (gt < NN) {
        int i = gt;
        float di = rsqrtf((float)(g_deg[i] + 1));
        g_deg[i] = 0;                 // self-clear for next graph replay
        g_dinv[i] = di;
        float x3 = x[i * 6 + 3], x4 = x[i * 6 + 4], x5 = x[i * 6 + 5];
        float d2 = di * di;
#pragma unroll
        for (int c = 0; c < 3; c++) {
            float xw = x3 * W1[9 + c] + x4 * W1[12 + c] + x5 * W1[15 + c];
            g_xw[i * 3 + c] = xw;
            g_acc[i * 3 + c] = d2 * xw;
        }
    }
    gsync(G1);

    // s2: scatter layer 1 (first-touch reads of g_xw/g_dinv: L1-cold, safe)
    if (gt < EE) {
        unsigned pk = g_pk[gt];
        if (pk != 0xFFFFFFFFu) {
            int s = pk & 2047, d = pk >> 11;
            float n = g_dinv[s] * g_dinv[d];
            atomicAdd(&g_acc[d * 3 + 0], n * g_xw[s * 3 + 0]);
            atomicAdd(&g_acc[d * 3 + 1], n * g_xw[s * 3 + 1]);
            atomicAdd(&g_acc[d * 3 + 2], n * g_xw[s * 3 + 2]);
        }
    }
    gsync(G1);

    // s3: node2 = leaky(acc+b1) -> xw2 + self term (acc via L2: atomics wrote it)
    if (gt < NN) {
        int i = gt;
        float h[3];
#pragma unroll
        for (int c = 0; c < 3; c++) {
            float v = __ldcg(&g_acc[i * 3 + c]) + b1[c];
            h[c] = (v >= 0.f) ? v : 0.2f * v;
        }
        float di = g_dinv[i];
        float d2 = di * di;
#pragma unroll
        for (int c = 0; c < 3; c++) {
            float xw = h[0] * W2[c] + h[1] * W2[3 + c] + h[2] * W2[6 + c];
            g_xw[i * 3 + c] = xw;
            g_acc[i * 3 + c] = d2 * xw;
        }
    }
    gsync(G1);

    // s4: scatter layer 2 (g_xw read in s2 then rewritten in s3 -> __ldcg)
    if (gt < EE) {
        unsigned pk = g_pk[gt];
        if (pk != 0xFFFFFFFFu) {
            int s = pk & 2047, d = pk >> 11;
            float n = g_dinv[s] * g_dinv[d];
            atomicAdd(&g_acc[d * 3 + 0], n * __ldcg(&g_xw[s * 3 + 0]));
            atomicAdd(&g_acc[d * 3 + 1], n * __ldcg(&g_xw[s * 3 + 1]));
            atomicAdd(&g_acc[d * 3 + 2], n * __ldcg(&g_xw[s * 3 + 2]));
        }
    }
    // leaky(acc + b2) fused into k_fc1's x-load (cross-launch: L1 flushed)
}

// ---------------- fc1 [2048 x 4185] with fused leaky(acc + b2) ---------------
__global__ void k_fc1(const float* __restrict__ W, const float* __restrict__ b,
                      const float* __restrict__ b2) {
    __shared__ __align__(16) float xs[4185];
    float bb0 = b2[0], bb1 = b2[1], bb2 = b2[2];
    for (int i = threadIdx.x; i < 4185; i += 256) {
        int c = i % 3;
        float bias = (c == 0) ? bb0 : (c == 1 ? bb1 : bb2);
        float v = g_acc[i] + bias;
        xs[i] = (v >= 0.f) ? v : 0.2f * v;
    }
    __syncthreads();
    int gt = blockIdx.x * 256 + threadIdx.x;
    int warp = gt >> 5, lane = gt & 31;
    if (warp >= 2048) return;
    const float* wr = W + (size_t)warp * 4185;
    float a = 0.f;
#pragma unroll 4
    for (int i = lane; i < 4185; i += 32) a += __ldcs(&wr[i]) * xs[i];
    a = warp_red(a);
    if (lane == 0) g_v1[warp] = a + b[warp];
}

// ---------------- fc2 [4096 x 2048] + seed conv accumulators -----------------
__global__ void k_fc2(const float* __restrict__ W, const float* __restrict__ b,
                      const float* __restrict__ c2_b, const float* __restrict__ c3_b,
                      const float* __restrict__ c4_b) {
    __shared__ __align__(16) float xs[2048];
    {
        int gt = blockIdx.x * 256 + threadIdx.x;
        int T = gridDim.x * 256;
        for (int i = gt; i < 32 * 54 * 54; i += T) g_c2[i] = c2_b[i / (54 * 54)];
        for (int i = gt; i < 64 * 52 * 52; i += T) g_c3[i] = c3_b[i / (52 * 52)];
        for (int i = gt; i < 64 * 50 * 50; i += T) g_c4[i] = c4_b[i / (50 * 50)];
    }
    for (int i = threadIdx.x; i < 2048; i += 256) xs[i] = g_v1[i];
    __syncthreads();
    int gt = blockIdx.x * 256 + threadIdx.x;
    int warp = gt >> 5, lane = gt & 31;
    if (warp >= 4096) return;
    const float4* w4 = (const float4*)(W + (size_t)warp * 2048);
    const float4* xs4 = (const float4*)xs;
    float a = 0.f;
#pragma unroll 4
    for (int i = lane; i < 512; i += 32) {
        float4 w = __ldcs(&w4[i]);
        float4 xv = xs4[i];
        a += w.x * xv.x + w.y * xv.y + w.z * xv.z + w.w * xv.w;
    }
    a = warp_red(a);
    if (lane == 0) g_v2[warp] = a + b[warp];
}

// ---------------- conv (CI-split, REDG accumulation) -------------------------
template <int CI, int KH, int KW, int OCB, int SPLIT>
__device__ __forceinline__ void conv_impl(const float* __restrict__ in,
                                          const float* __restrict__ w,
                                          const float* __restrict__ bia,
                                          float* __restrict__ out,
                                          int H, int W, int OH, int OW) {
    const int CIP = CI / SPLIT;
    __shared__ float sw[OCB * CIP * KH * KW];
    int ocg = blockIdx.x / SPLIT;
    int part = blockIdx.x - ocg * SPLIT;
    int oc0 = ocg * OCB;
    int ic0 = part * CIP;
    for (int i = threadIdx.x; i < OCB * CIP * KH * KW; i += blockDim.x) {
        int o = i / (CIP * KH * KW);
        int rem = i - o * (CIP * KH * KW);
        int ic = rem / (KH * KW);
        int k = rem - ic * (KH * KW);
        sw[i] = w[((size_t)(oc0 + o) * CI + ic0 + ic) * (KH * KW) + k];
    }
    __syncthreads();

    int p = blockIdx.y * blockDim.x + threadIdx.x;
    if (p >= OH * OW) return;
    int oy = p / OW, ox = p - oy * OW;
    float acc[OCB];
#pragma unroll
    for (int o = 0; o < OCB; o++) acc[o] = (SPLIT == 1) ? bia[oc0 + o] : 0.f;

    for (int ic = 0; ic < CIP; ic++) {
        const float* ip = in + ((size_t)(ic0 + ic) * H + oy) * W + ox;
        const float* wp = sw + ic * KH * KW;
#pragma unroll
        for (int i = 0; i < KH; i++)
#pragma unroll
            for (int j = 0; j < KW; j++) {
                float v = ip[i * W + j];
#pragma unroll
                for (int o = 0; o < OCB; o++)
                    acc[o] += wp[o * CIP * KH * KW + i * KW + j] * v;
            }
    }
#pragma unroll
    for (int o = 0; o < OCB; o++) {
        size_t oi = ((size_t)(oc0 + o) * OH + oy) * OW + ox;
        if (SPLIT == 1) out[oi] = acc[o];
        else atomicAdd(&out[oi], acc[o]);
    }
}

__global__ void k_conv1(const float* __restrict__ w, const float* __restrict__ b) {
    conv_impl<1, 7, 7, 4, 1>(g_v2, w, b, g_c1, 64, 64, 58, 58);
}
__global__ void k_conv2(const float* __restrict__ w, const float* __restrict__ b) {
    conv_impl<32, 5, 5, 4, 4>(g_c1, w, b, g_c2, 58, 58, 54, 54);
}
__global__ void k_conv3(const float* __restrict__ w, const float* __restrict__ b) {
    conv_impl<32, 3, 3, 8, 2>(g_c2, w, b, g_c3, 54, 54, 52, 52);
}
__global__ void k_conv4(const float* __restrict__ w, const float* __restrict__ b) {
    conv_impl<64, 3, 3, 8, 4>(g_c3, w, b, g_c4, 52, 52, 50, 50);
}

// ---------------- kB: fc3 (8-row groups) + fc4 + fc5 (R9 proven) -------------
extern "C" __global__ void __launch_bounds__(256, 4) kB(
    const float* __restrict__ fc3_w,
    const float* __restrict__ fc4_w, const float* __restrict__ fc4_b,
    const float* __restrict__ fc5_w, const float* __restrict__ fc5_b,
    float* __restrict__ out) {
    __shared__ __align__(16) float xs[2048];
    __shared__ float sred[8];

    // fc3: 2048x160000. 4096 chunks = 256 row-groups(8 rows) x 16 col-splits.
    const int NC4 = 40000, CHUNK = 2500, NCHUNK = 4096;
    for (int c = blockIdx.x; c < NCHUNK; c += GB) {
        int rg = c >> 4, cs = c & 15;
        int r0 = rg * 8;
        if (threadIdx.x < 8) sred[threadIdx.x] = 0.f;
        __syncthreads();
        const float4* x4 = (const float4*)g_c4 + cs * CHUNK;
        const float4* w4 = (const float4*)fc3_w + (size_t)r0 * NC4 + cs * CHUNK;
        float a[8];
#pragma unroll
        for (int k = 0; k < 8; k++) a[k] = 0.f;
        for (int i = threadIdx.x; i < CHUNK; i += 256) {
            float4 xv = x4[i];
#pragma unroll
            for (int k = 0; k < 8; k++) {
                float4 w = __ldcs(&w4[i + k * NC4]);
                a[k] += w.x * xv.x + w.y * xv.y + w.z * xv.z + w.w * xv.w;
            }
        }
#pragma unroll
        for (int k = 0; k < 8; k++) a[k] = warp_red(a[k]);
        if ((threadIdx.x & 31) == 0) {
#pragma unroll
            for (int k = 0; k < 8; k++) atomicAdd(&sred[k], a[k]);
        }
        __syncthreads();
        if (threadIdx.x < 8) atomicAdd(&g_f3[r0 + threadIdx.x], sred[threadIdx.x]);
        __syncthreads();
    }
    gsync(GB);

    // fc4: 2048x2048, warp per row
    {
        for (int i = threadIdx.x; i < 2048; i += 256) xs[i] = __ldcg(&g_f3[i]);
        __syncthreads();
        int gt = blockIdx.x * 256 + threadIdx.x;
        int warp = gt >> 5, lane = gt & 31, nwarp = (GB * 256) >> 5;
        const float4* xs4 = (const float4*)xs;
        for (int r = warp; r < 2048; r += nwarp) {
            const float4* w4 = (const float4*)(fc4_w + (size_t)r * 2048);
            float a = 0.f;
#pragma unroll 4
            for (int i = lane; i < 512; i += 32) {
                float4 w = __ldcs(&w4[i]);
                float4 xv = xs4[i];
                a += w.x * xv.x + w.y * xv.y + w.z * xv.z + w.w * xv.w;
            }
            a = warp_red(a);
            if (lane == 0) g_f4[r] = a + fc4_b[r];
        }
    }
    gsync(GB);

    // fc5: 48x2048 -> out
    {
        for (int i = threadIdx.x; i < 2048; i += 256) xs[i] = __ldcg(&g_f4[i]);
        __syncthreads();
        int gt = blockIdx.x * 256 + threadIdx.x;
        int warp = gt >> 5, lane = gt & 31;
        if (warp < 48) {
            const float4* w4 = (const float4*)(fc5_w + (size_t)warp * 2048);
            const float4* xs4 = (const float4*)xs;
            float a = 0.f;
            for (int i = lane; i < 512; i += 32) {
                float4 w = w4[i];
                float4 xv = xs4[i];
                a += w.x * xv.x + w.y * xv.y + w.z * xv.z + w.w * xv.w;
            }
            a = warp_red(a);
            if (lane == 0) out[warp] = a + fc5_b[warp];
        }
    }
}

// ---------------- launcher ---------------------------------------------------
extern "C" void kernel_launch(void* const* d_in, const int* in_sizes, int n_in,
                              void* d_out, int out_size) {
    const float* x     = (const float*)d_in[0];
    const void*  ei    = d_in[1];
    const float* W1    = (const float*)d_in[2];
    const float* b1    = (const float*)d_in[3];
    const float* W2    = (const float*)d_in[4];
    const float* b2    = (const float*)d_in[5];
    const float* fc1_w = (const float*)d_in[6];
    const float* fc1_b = (const float*)d_in[7];
    const float* fc2_w = (const float*)d_in[8];
    const float* fc2_b = (const float*)d_in[9];
    const float* c1_w  = (const float*)d_in[10];
    const float* c1_b  = (const float*)d_in[11];
    const float* c2_w  = (const float*)d_in[12];
    const float* c2_b  = (const float*)d_in[13];
    const float* c3_w  = (const float*)d_in[14];
    const float* c3_b  = (const float*)d_in[15];
    const float* c4_w  = (const float*)d_in[16];
    const float* c4_b  = (const float*)d_in[17];
    const float* fc3_w = (const float*)d_in[18];
    const float* fc3_b = (const float*)d_in[19];
    const float* fc4_w = (const float*)d_in[20];
    const float* fc4_b = (const float*)d_in[21];
    const float* fc5_w = (const float*)d_in[22];
    const float* fc5_b = (const float*)d_in[23];
    float* out = (float*)d_out;

    // whole GCN in one persistent launch (replaces 5 launches)
    k_gcn<<<G1, 256>>>(x, ei, W1, b1, W2, fc3_b);

    k_fc1<<<256, 256>>>(fc1_w, fc1_b, b2);
    k_fc2<<<512, 256>>>(fc2_w, fc2_b, c2_b, c3_b, c4_b);

    {
        dim3 g1(8, (58 * 58 + 255) / 256);
        k_conv1<<<g1, 256>>>(c1_w, c1_b);
        dim3 g2(32, (54 * 54 + 255) / 256);
        k_conv2<<<g2, 256>>>(c2_w, c2_b);
        dim3 g3(16, (52 * 52 + 255) / 256);
        k_conv3<<<g3, 256>>>(c3_w, c3_b);
        dim3 g4(32, (50 * 50 + 255) / 256);
        k_conv4<<<g4, 256>>>(c4_w, c4_b);
    }

    kB<<<GB, 256>>>(fc3_w, fc4_w, fc4_b, fc5_w, fc5_b, out);
}